// round 5
// baseline (speedup 1.0000x reference)
#include <cuda_runtime.h>
#include <math.h>

// PhaseMoE: v[b,:] = sum_k p_hat[b,k] * (silu(silu(x W1k + b1k) W2k + b2k) W3k + b3k)
// x = concat(u[256], cond[1024], tau[1])  -> 1281
// B=32768, K=8, HID=128, LATENT=256
//
// Fully fused: one CTA handles 32 tokens, loops over all 8 experts, all
// intermediates live in shared memory / registers. FFMA-bound baseline.

#define TB 32   // tokens per block

__global__ __launch_bounds__(256, 2)
void phase_moe_kernel(const float* __restrict__ cond,
                      const float* __restrict__ u,
                      const float* __restrict__ tau,
                      const float* __restrict__ p_hat,
                      const float* __restrict__ W1,
                      const float* __restrict__ b1,
                      const float* __restrict__ W2,
                      const float* __restrict__ b2,
                      const float* __restrict__ W3,
                      const float* __restrict__ b3,
                      float* __restrict__ out)
{
    // 48 KB static smem total (fits default limit, no attribute needed):
    __shared__ float wbuf[32 * 128];   // 16 KB weight tile; layer3 views as [16][256]
    __shared__ float h1s[TB][128];     // 16 KB
    __shared__ float h2s[TB][128];     // 16 KB; first 1024 floats double as xs[32][32]

    float* xs = &h2s[0][0];            // alias: xs dead before h2s is written

    const int t  = threadIdx.x;
    const int ti = t >> 5;             // 0..7
    const int tj = t & 31;             // 0..31
    const int b0 = blockIdx.x * TB;
    const int r0 = ti * 4;             // this thread's row base (4 rows)

    // Output accumulator: rows r0..r0+3, cols tj*8..tj*8+7
    float vacc[32];
#pragma unroll
    for (int i = 0; i < 32; ++i) vacc[i] = 0.f;

    for (int k = 0; k < 8; ++k) {
        //================= layer 1: h1 = silu(x @ W1k + b1k), x: 32 x 1281 =====
        float acc[16];  // rows r0+r, cols tj*4+c
#pragma unroll
        for (int c = 0; c < 4; ++c) {
            float bv = b1[k * 128 + tj * 4 + c];
#pragma unroll
            for (int r = 0; r < 4; ++r) acc[r * 4 + c] = bv;
        }
        const float* W1k = W1 + (size_t)k * 1281 * 128;

        for (int kc0 = 0; kc0 < 1281; kc0 += 32) {
            __syncthreads();  // prior smem reads (and h2s/xs reuse) complete
            // ---- stage xs[32][32] (zero-fill past 1281) ----
#pragma unroll
            for (int q = 0; q < 4; ++q) {
                int idx = t + q * 256;
                int row = idx >> 5;
                int kk  = idx & 31;
                int g   = kc0 + kk;
                float v = 0.f;
                if (g < 1281) {
                    int gb = b0 + row;
                    if (g < 256)        v = u[gb * 256 + g];
                    else if (g < 1280)  v = cond[gb * 1024 + (g - 256)];
                    else                v = tau[gb];
                }
                xs[row * 32 + kk] = v;
            }
            // ---- stage wbuf[32][128] via float4 (zero-fill past 1281) ----
#pragma unroll
            for (int q = 0; q < 4; ++q) {
                int f  = t + q * 256;   // float4 index, 1024 total
                int kk = f >> 5;        // 32 float4 per 128-wide row
                int c4 = f & 31;
                int g  = kc0 + kk;
                float4 v = make_float4(0.f, 0.f, 0.f, 0.f);
                if (g < 1281)
                    v = *reinterpret_cast<const float4*>(&W1k[g * 128 + c4 * 4]);
                *reinterpret_cast<float4*>(&wbuf[kk * 128 + c4 * 4]) = v;
            }
            __syncthreads();
            // ---- 32x128 += 32x32 @ 32x128 ----
#pragma unroll
            for (int kk = 0; kk < 32; ++kk) {
                float4 bw = *reinterpret_cast<const float4*>(&wbuf[kk * 128 + tj * 4]);
#pragma unroll
                for (int r = 0; r < 4; ++r) {
                    float a = xs[(r0 + r) * 32 + kk];   // warp-broadcast
                    acc[r * 4 + 0] = fmaf(a, bw.x, acc[r * 4 + 0]);
                    acc[r * 4 + 1] = fmaf(a, bw.y, acc[r * 4 + 1]);
                    acc[r * 4 + 2] = fmaf(a, bw.z, acc[r * 4 + 2]);
                    acc[r * 4 + 3] = fmaf(a, bw.w, acc[r * 4 + 3]);
                }
            }
        }
        // silu -> h1s (own elements; layer2's first sync orders the reads)
#pragma unroll
        for (int r = 0; r < 4; ++r)
#pragma unroll
            for (int c = 0; c < 4; ++c) {
                float x = acc[r * 4 + c];
                h1s[r0 + r][tj * 4 + c] = x / (1.f + __expf(-x));
            }

        //================= layer 2: h2 = silu(h1 @ W2k + b2k), 128 -> 128 =====
#pragma unroll
        for (int c = 0; c < 4; ++c) {
            float bv = b2[k * 128 + tj * 4 + c];
#pragma unroll
            for (int r = 0; r < 4; ++r) acc[r * 4 + c] = bv;
        }
        const float* W2k = W2 + (size_t)k * 128 * 128;
        for (int kc0 = 0; kc0 < 128; kc0 += 32) {
            __syncthreads();
#pragma unroll
            for (int q = 0; q < 4; ++q) {
                int f  = t + q * 256;
                int kk = f >> 5;
                int c4 = f & 31;
                *reinterpret_cast<float4*>(&wbuf[kk * 128 + c4 * 4]) =
                    *reinterpret_cast<const float4*>(&W2k[(kc0 + kk) * 128 + c4 * 4]);
            }
            __syncthreads();
#pragma unroll
            for (int kk = 0; kk < 32; ++kk) {
                float4 bw = *reinterpret_cast<const float4*>(&wbuf[kk * 128 + tj * 4]);
#pragma unroll
                for (int r = 0; r < 4; ++r) {
                    float a = h1s[r0 + r][kc0 + kk];
                    acc[r * 4 + 0] = fmaf(a, bw.x, acc[r * 4 + 0]);
                    acc[r * 4 + 1] = fmaf(a, bw.y, acc[r * 4 + 1]);
                    acc[r * 4 + 2] = fmaf(a, bw.z, acc[r * 4 + 2]);
                    acc[r * 4 + 3] = fmaf(a, bw.w, acc[r * 4 + 3]);
                }
            }
        }
        // silu -> h2s (xs alias is dead; own elements only)
#pragma unroll
        for (int r = 0; r < 4; ++r)
#pragma unroll
            for (int c = 0; c < 4; ++c) {
                float x = acc[r * 4 + c];
                h2s[r0 + r][tj * 4 + c] = x / (1.f + __expf(-x));
            }

        //================= layer 3: e3 = h2 @ W3k + b3k, 128 -> 256 ===========
        float e3[32];  // rows r0+r, cols tj*8+c
#pragma unroll
        for (int c = 0; c < 8; ++c) {
            float bv = b3[k * 256 + tj * 8 + c];
#pragma unroll
            for (int r = 0; r < 4; ++r) e3[r * 8 + c] = bv;
        }
        const float* W3k = W3 + (size_t)k * 128 * 256;
        for (int kc0 = 0; kc0 < 128; kc0 += 16) {
            __syncthreads();
            // wbuf viewed as [16][256]: 4096 floats = 1024 float4
#pragma unroll
            for (int q = 0; q < 4; ++q) {
                int f  = t + q * 256;
                int kk = f >> 6;        // 64 float4 per 256-wide row
                int c4 = f & 63;
                *reinterpret_cast<float4*>(&wbuf[kk * 256 + c4 * 4]) =
                    *reinterpret_cast<const float4*>(&W3k[(kc0 + kk) * 256 + c4 * 4]);
            }
            __syncthreads();
#pragma unroll
            for (int kk = 0; kk < 16; ++kk) {
                float4 bw0 = *reinterpret_cast<const float4*>(&wbuf[kk * 256 + tj * 8]);
                float4 bw1 = *reinterpret_cast<const float4*>(&wbuf[kk * 256 + tj * 8 + 4]);
#pragma unroll
                for (int r = 0; r < 4; ++r) {
                    float a = h2s[r0 + r][kc0 + kk];
                    e3[r * 8 + 0] = fmaf(a, bw0.x, e3[r * 8 + 0]);
                    e3[r * 8 + 1] = fmaf(a, bw0.y, e3[r * 8 + 1]);
                    e3[r * 8 + 2] = fmaf(a, bw0.z, e3[r * 8 + 2]);
                    e3[r * 8 + 3] = fmaf(a, bw0.w, e3[r * 8 + 3]);
                    e3[r * 8 + 4] = fmaf(a, bw1.x, e3[r * 8 + 4]);
                    e3[r * 8 + 5] = fmaf(a, bw1.y, e3[r * 8 + 5]);
                    e3[r * 8 + 6] = fmaf(a, bw1.z, e3[r * 8 + 6]);
                    e3[r * 8 + 7] = fmaf(a, bw1.w, e3[r * 8 + 7]);
                }
            }
        }
        // gate-weighted accumulate
#pragma unroll
        for (int r = 0; r < 4; ++r) {
            float p = p_hat[(size_t)(b0 + r0 + r) * 8 + k];
#pragma unroll
            for (int c = 0; c < 8; ++c)
                vacc[r * 8 + c] = fmaf(p, e3[r * 8 + c], vacc[r * 8 + c]);
        }
    }  // experts

    // epilogue: vectorized stores
#pragma unroll
    for (int r = 0; r < 4; ++r) {
        float4 o0 = make_float4(vacc[r * 8 + 0], vacc[r * 8 + 1],
                                vacc[r * 8 + 2], vacc[r * 8 + 3]);
        float4 o1 = make_float4(vacc[r * 8 + 4], vacc[r * 8 + 5],
                                vacc[r * 8 + 6], vacc[r * 8 + 7]);
        float* orow = out + (size_t)(b0 + r0 + r) * 256 + tj * 8;
        *reinterpret_cast<float4*>(orow)     = o0;
        *reinterpret_cast<float4*>(orow + 4) = o1;
    }
}

extern "C" void kernel_launch(void* const* d_in, const int* in_sizes, int n_in,
                              void* d_out, int out_size) {
    const float* cond = (const float*)d_in[0];
    const float* u    = (const float*)d_in[1];
    const float* tau  = (const float*)d_in[2];
    const float* p    = (const float*)d_in[3];
    const float* W1   = (const float*)d_in[4];
    const float* b1   = (const float*)d_in[5];
    const float* W2   = (const float*)d_in[6];
    const float* b2   = (const float*)d_in[7];
    const float* W3   = (const float*)d_in[8];
    const float* b3   = (const float*)d_in[9];
    float* out = (float*)d_out;

    phase_moe_kernel<<<32768 / TB, 256>>>(cond, u, tau, p,
                                          W1, b1, W2, b2, W3, b3, out);
}

// round 7
// speedup vs baseline: 2.8106x; 2.8106x over previous
#include <cuda_runtime.h>
#include <cuda_bf16.h>
#include <cstdint>

// ============================================================================
// PhaseMoE via mma.sync (HMMA m16n8k16 bf16) with hi/lo 3-MMA split.
//   v[b,:] = sum_k p[b,k] * (silu(silu(x W1k+b1k) W2k+b2k) W3k + b3k)
//   x = concat(u[256], cond[1024], tau[1]); tau handled as rank-1 epilogue.
//   p folded into h2; out initialized to sum_k p_k*b3_k, then += D3 per expert.
// NOTE: tcgen05 is NOT available (harness PTX pass targets compute_103, not
// 103a). Everything here is sm_80+ legal: mma.sync + cp.async.
// ============================================================================

#define B_TOK 32768
#define KEXP  8
#define EIN   1280
#define HID   128
#define LAT   256

#define ROWB   80            // padded bytes per 32-elem bf16 row (16B-aligned, bank-spread)
#define TILEB  (128 * ROWB)  // 10240 bytes per 128x32 tile

// smem map (dynamic):
#define STG(s, t) ((uint32_t)((s) * 4 * TILEB + (t) * TILEB))        // t:0 Ahi,1 Alo,2 Bhi,3 Blo
#define HOF(c, h) ((uint32_t)(8 * TILEB + ((c) * 2 + (h)) * TILEB))  // h tiles, 4 chunks x hi/lo
#define AUX       ((uint32_t)(16 * TILEB))                           // 163840
#define SMEM_TOTAL (16 * TILEB + 2048)                               // 165888

// ---- bf16 hi/lo scratch (__device__ globals: allocation-free) ----
__device__ __align__(16) __nv_bfloat16 g_xhi[(size_t)B_TOK * EIN];
__device__ __align__(16) __nv_bfloat16 g_xlo[(size_t)B_TOK * EIN];
__device__ __align__(16) __nv_bfloat16 g_w1hi[KEXP * HID * EIN];   // [e][n][k]
__device__ __align__(16) __nv_bfloat16 g_w1lo[KEXP * HID * EIN];
__device__ __align__(16) __nv_bfloat16 g_w2hi[KEXP * HID * HID];
__device__ __align__(16) __nv_bfloat16 g_w2lo[KEXP * HID * HID];
__device__ __align__(16) __nv_bfloat16 g_w3hi[KEXP * LAT * HID];
__device__ __align__(16) __nv_bfloat16 g_w3lo[KEXP * LAT * HID];

// ============================ helpers =======================================
__device__ __forceinline__ uint32_t smem_u32(const void* p) {
    uint32_t a;
    asm("{ .reg .u64 t; cvta.to.shared.u64 t, %1; cvt.u32.u64 %0, t; }"
        : "=r"(a) : "l"(p));
    return a;
}
__device__ __forceinline__ void cpasync16(uint32_t dst, const void* src) {
    asm volatile("cp.async.cg.shared.global [%0], [%1], 16;"
                 :: "r"(dst), "l"(src));
}
#define CP_COMMIT() asm volatile("cp.async.commit_group;" ::: "memory")
#define CP_WAIT1()  asm volatile("cp.async.wait_group 1;" ::: "memory")
#define CP_WAIT0()  asm volatile("cp.async.wait_group 0;" ::: "memory")

__device__ __forceinline__ void mma16816(float* c,
        uint32_t a0, uint32_t a1, uint32_t a2, uint32_t a3,
        uint32_t b0, uint32_t b1) {
    asm volatile(
        "mma.sync.aligned.m16n8k16.row.col.f32.bf16.bf16.f32 "
        "{%0,%1,%2,%3}, {%4,%5,%6,%7}, {%8,%9}, {%0,%1,%2,%3};"
        : "+f"(c[0]), "+f"(c[1]), "+f"(c[2]), "+f"(c[3])
        : "r"(a0), "r"(a1), "r"(a2), "r"(a3), "r"(b0), "r"(b1));
}

// stage a 128-row x 32-bf16 tile (64B payload/row, ROWB-padded) via cp.async
__device__ __forceinline__ void stage_tile(uint32_t sb, uint32_t dst,
        const __nv_bfloat16* __restrict__ src, int ldk, int tid) {
#pragma unroll
    for (int i = 0; i < 2; ++i) {
        int idx = tid + i * 256;          // 0..511
        int row = idx >> 2, c16 = idx & 3;
        cpasync16(sb + dst + row * ROWB + c16 * 16,
                  (const char*)src + (size_t)row * ldk * 2 + c16 * 16);
    }
}

// one 32-wide K chunk of the 3-MMA split: c[2][8][4] += A(128x32) * B(128x32)^T
__device__ __forceinline__ void mma_chunk(float c[2][8][4], const char* smem,
        uint32_t Ahi, uint32_t Alo, uint32_t Bhi, uint32_t Blo,
        int wm, int wn, int lr, int lc) {
#pragma unroll
    for (int ks = 0; ks < 2; ++ks) {
        const int kb = (ks * 16 + lc * 2) * 2;   // byte offset along k
        uint32_t ah[2][4], al[2][4];
#pragma unroll
        for (int mt = 0; mt < 2; ++mt) {
            uint32_t base = (uint32_t)((wm * 32 + mt * 16 + lr) * ROWB + kb);
            ah[mt][0] = *(const uint32_t*)(smem + Ahi + base);
            ah[mt][1] = *(const uint32_t*)(smem + Ahi + base + 8 * ROWB);
            ah[mt][2] = *(const uint32_t*)(smem + Ahi + base + 16);
            ah[mt][3] = *(const uint32_t*)(smem + Ahi + base + 8 * ROWB + 16);
            al[mt][0] = *(const uint32_t*)(smem + Alo + base);
            al[mt][1] = *(const uint32_t*)(smem + Alo + base + 8 * ROWB);
            al[mt][2] = *(const uint32_t*)(smem + Alo + base + 16);
            al[mt][3] = *(const uint32_t*)(smem + Alo + base + 8 * ROWB + 16);
        }
        uint32_t bh[8][2], bl[8][2];
#pragma unroll
        for (int nt = 0; nt < 8; ++nt) {
            uint32_t base = (uint32_t)((wn * 64 + nt * 8 + lr) * ROWB + kb);
            bh[nt][0] = *(const uint32_t*)(smem + Bhi + base);
            bh[nt][1] = *(const uint32_t*)(smem + Bhi + base + 16);
            bl[nt][0] = *(const uint32_t*)(smem + Blo + base);
            bl[nt][1] = *(const uint32_t*)(smem + Blo + base + 16);
        }
#pragma unroll
        for (int mt = 0; mt < 2; ++mt)
#pragma unroll
            for (int nt = 0; nt < 8; ++nt) {
                mma16816(c[mt][nt], ah[mt][0], ah[mt][1], ah[mt][2], ah[mt][3],
                         bh[nt][0], bh[nt][1]);
                mma16816(c[mt][nt], ah[mt][0], ah[mt][1], ah[mt][2], ah[mt][3],
                         bl[nt][0], bl[nt][1]);
                mma16816(c[mt][nt], al[mt][0], al[mt][1], al[mt][2], al[mt][3],
                         bh[nt][0], bh[nt][1]);
            }
    }
}

__device__ __forceinline__ void split_pack(float h0, float h1,
                                           uint32_t& hip, uint32_t& lop) {
    __nv_bfloat16 h0h = __float2bfloat16(h0);
    __nv_bfloat16 h1h = __float2bfloat16(h1);
    hip = (uint32_t)__bfloat16_as_ushort(h0h) |
          ((uint32_t)__bfloat16_as_ushort(h1h) << 16);
    lop = (uint32_t)__bfloat16_as_ushort(__float2bfloat16(h0 - __bfloat162float(h0h))) |
          ((uint32_t)__bfloat16_as_ushort(__float2bfloat16(h1 - __bfloat162float(h1h))) << 16);
}

// ======================= prep kernels =======================================
__global__ void convert_x_kernel(const float* __restrict__ u,
                                 const float* __restrict__ cond) {
    const int total = B_TOK * EIN;
    for (int i = blockIdx.x * blockDim.x + threadIdx.x; i < total;
         i += gridDim.x * blockDim.x) {
        int b = i / EIN, k = i - b * EIN;
        float v = (k < 256) ? u[(size_t)b * 256 + k]
                            : cond[(size_t)b * 1024 + (k - 256)];
        __nv_bfloat16 hi = __float2bfloat16(v);
        g_xhi[i] = hi;
        g_xlo[i] = __float2bfloat16(v - __bfloat162float(hi));
    }
}

__global__ void convert_w_kernel(const float* __restrict__ W1,
                                 const float* __restrict__ W2,
                                 const float* __restrict__ W3) {
    const int N1 = KEXP * HID * EIN;
    const int N2 = KEXP * HID * HID;
    const int N3 = KEXP * LAT * HID;
    const int total = N1 + N2 + N3;
    for (int i = blockIdx.x * blockDim.x + threadIdx.x; i < total;
         i += gridDim.x * blockDim.x) {
        float v;
        __nv_bfloat16 *dh, *dl;
        if (i < N1) {
            int e = i / (HID * EIN), r = i - e * (HID * EIN);
            int n = r / EIN, k = r - n * EIN;
            v = W1[((size_t)e * 1281 + k) * HID + n];
            dh = &g_w1hi[i]; dl = &g_w1lo[i];
        } else if (i < N1 + N2) {
            int j = i - N1;
            int e = j / (HID * HID), r = j - e * (HID * HID);
            int n = r / HID, k = r - n * HID;
            v = W2[((size_t)e * HID + k) * HID + n];
            dh = &g_w2hi[j]; dl = &g_w2lo[j];
        } else {
            int j = i - N1 - N2;
            int e = j / (LAT * HID), r = j - e * (LAT * HID);
            int n = r / HID, k = r - n * HID;
            v = W3[((size_t)e * HID + k) * LAT + n];
            dh = &g_w3hi[j]; dl = &g_w3lo[j];
        }
        __nv_bfloat16 hi = __float2bfloat16(v);
        *dh = hi;
        *dl = __float2bfloat16(v - __bfloat162float(hi));
    }
}

__global__ void init_out_kernel(const float* __restrict__ p_hat,
                                const float* __restrict__ b3,
                                float* __restrict__ out) {
    int i = blockIdx.x * blockDim.x + threadIdx.x;   // over B_TOK*LAT
    int b = i >> 8, c = i & 255;
    float s = 0.f;
#pragma unroll
    for (int k = 0; k < KEXP; ++k)
        s = fmaf(p_hat[(size_t)b * KEXP + k], b3[k * LAT + c], s);
    out[i] = s;
}

// =========================== main kernel ====================================
__global__ __launch_bounds__(256, 1)
void phase_moe_mma(const float* __restrict__ tau,
                   const float* __restrict__ p_hat,
                   const float* __restrict__ W1,
                   const float* __restrict__ b1,
                   const float* __restrict__ b2,
                   float* __restrict__ out) {
    extern __shared__ __align__(128) char smem[];
    const uint32_t sb = smem_u32(smem);
    const int tid = threadIdx.x;
    const int w   = tid >> 5;
    const int wm  = w >> 1, wn = w & 1;
    const int lr  = (tid & 31) >> 2, lc = tid & 3;
    const int b0  = blockIdx.x * 128;

    float* b1s  = reinterpret_cast<float*>(smem + AUX);          // 128
    float* b2s  = reinterpret_cast<float*>(smem + AUX + 512);    // 128
    float* w1l  = reinterpret_cast<float*>(smem + AUX + 1024);   // 128
    float* taus = reinterpret_cast<float*>(smem + AUX + 1536);   // 128

    if (tid < 128) taus[tid] = tau[b0 + tid];

    float c[2][8][4];

    for (int e = 0; e < KEXP; ++e) {
        __syncthreads();
        if (tid < 128) {
            b1s[tid] = b1[e * HID + tid];
            b2s[tid] = b2[e * HID + tid];
            w1l[tid] = W1[((size_t)e * 1281 + 1280) * HID + tid];
        }

#pragma unroll
        for (int mt = 0; mt < 2; ++mt)
#pragma unroll
            for (int nt = 0; nt < 8; ++nt)
#pragma unroll
                for (int q = 0; q < 4; ++q) c[mt][nt][q] = 0.f;

        // ---------------- layer 1: K=1280, 40 chunks -----------------------
        const __nv_bfloat16* xh = g_xhi + (size_t)b0 * EIN;
        const __nv_bfloat16* xl = g_xlo + (size_t)b0 * EIN;
        const __nv_bfloat16* w1h = g_w1hi + (size_t)e * HID * EIN;
        const __nv_bfloat16* w1lo = g_w1lo + (size_t)e * HID * EIN;

        stage_tile(sb, STG(0, 0), xh,   EIN, tid);
        stage_tile(sb, STG(0, 1), xl,   EIN, tid);
        stage_tile(sb, STG(0, 2), w1h,  EIN, tid);
        stage_tile(sb, STG(0, 3), w1lo, EIN, tid);
        CP_COMMIT();
        for (int ch = 0; ch < 40; ++ch) {
            if (ch < 39) {
                int s = (ch + 1) & 1, ko = (ch + 1) * 32;
                stage_tile(sb, STG(s, 0), xh + ko,   EIN, tid);
                stage_tile(sb, STG(s, 1), xl + ko,   EIN, tid);
                stage_tile(sb, STG(s, 2), w1h + ko,  EIN, tid);
                stage_tile(sb, STG(s, 3), w1lo + ko, EIN, tid);
                CP_COMMIT();
                CP_WAIT1();
            } else {
                CP_WAIT0();
            }
            __syncthreads();
            int s = ch & 1;
            mma_chunk(c, smem, STG(s, 0), STG(s, 1), STG(s, 2), STG(s, 3),
                      wm, wn, lr, lc);
            __syncthreads();
        }

        // prefetch layer-2 B chunk 0 (overlaps epilogue)
        const __nv_bfloat16* w2h = g_w2hi + (size_t)e * HID * HID;
        const __nv_bfloat16* w2l = g_w2lo + (size_t)e * HID * HID;
        stage_tile(sb, STG(0, 2), w2h, HID, tid);
        stage_tile(sb, STG(0, 3), w2l, HID, tid);
        CP_COMMIT();

        // L1 epilogue: +bias +tau*w1last, silu, split -> h tiles
#pragma unroll
        for (int mt = 0; mt < 2; ++mt)
#pragma unroll
            for (int nt = 0; nt < 8; ++nt)
#pragma unroll
                for (int pr = 0; pr < 2; ++pr) {
                    int m   = wm * 32 + mt * 16 + lr + pr * 8;
                    int col = wn * 64 + nt * 8 + lc * 2;
                    float t = taus[m];
                    float v0 = c[mt][nt][pr * 2]     + b1s[col]     + t * w1l[col];
                    float v1 = c[mt][nt][pr * 2 + 1] + b1s[col + 1] + t * w1l[col + 1];
                    float h0 = v0 / (1.f + __expf(-v0));
                    float h1 = v1 / (1.f + __expf(-v1));
                    uint32_t hip, lop;
                    split_pack(h0, h1, hip, lop);
                    uint32_t byte = (uint32_t)(m * ROWB + (col & 31) * 2);
                    int chk = col >> 5;
                    *(uint32_t*)(smem + HOF(chk, 0) + byte) = hip;
                    *(uint32_t*)(smem + HOF(chk, 1) + byte) = lop;
                }

        // ---------------- layer 2: K=128, 4 chunks --------------------------
#pragma unroll
        for (int mt = 0; mt < 2; ++mt)
#pragma unroll
            for (int nt = 0; nt < 8; ++nt) {
                float tmp0[4];
#pragma unroll
                for (int q = 0; q < 4; ++q) { tmp0[q] = 0.f; c[mt][nt][q] = 0.f; }
                (void)tmp0;
            }
        for (int ch = 0; ch < 4; ++ch) {
            if (ch < 3) {
                int s = (ch + 1) & 1, ko = (ch + 1) * 32;
                stage_tile(sb, STG(s, 2), w2h + ko, HID, tid);
                stage_tile(sb, STG(s, 3), w2l + ko, HID, tid);
                CP_COMMIT();
                CP_WAIT1();
            } else {
                CP_WAIT0();
            }
            __syncthreads();
            int s = ch & 1;
            mma_chunk(c, smem, HOF(ch, 0), HOF(ch, 1), STG(s, 2), STG(s, 3),
                      wm, wn, lr, lc);
            __syncthreads();
        }

        // prefetch layer-3 nh=0 chunk 0
        const __nv_bfloat16* w3h = g_w3hi + (size_t)e * LAT * HID;
        const __nv_bfloat16* w3l = g_w3lo + (size_t)e * LAT * HID;
        stage_tile(sb, STG(0, 2), w3h, HID, tid);
        stage_tile(sb, STG(0, 3), w3l, HID, tid);
        CP_COMMIT();

        // L2 epilogue: +bias, silu, *p -> h tiles
#pragma unroll
        for (int mt = 0; mt < 2; ++mt)
#pragma unroll
            for (int nt = 0; nt < 8; ++nt)
#pragma unroll
                for (int pr = 0; pr < 2; ++pr) {
                    int m   = wm * 32 + mt * 16 + lr + pr * 8;
                    int col = wn * 64 + nt * 8 + lc * 2;
                    float pe = p_hat[(size_t)(b0 + m) * KEXP + e];
                    float v0 = c[mt][nt][pr * 2]     + b2s[col];
                    float v1 = c[mt][nt][pr * 2 + 1] + b2s[col + 1];
                    float h0 = pe * (v0 / (1.f + __expf(-v0)));
                    float h1 = pe * (v1 / (1.f + __expf(-v1)));
                    uint32_t hip, lop;
                    split_pack(h0, h1, hip, lop);
                    uint32_t byte = (uint32_t)(m * ROWB + (col & 31) * 2);
                    int chk = col >> 5;
                    *(uint32_t*)(smem + HOF(chk, 0) + byte) = hip;
                    *(uint32_t*)(smem + HOF(chk, 1) + byte) = lop;
                }

        // ---------------- layer 3: two 128-col halves, K=128 ----------------
        for (int nh = 0; nh < 2; ++nh) {
            const __nv_bfloat16* bh = w3h + (size_t)nh * 128 * HID;
            const __nv_bfloat16* bl = w3l + (size_t)nh * 128 * HID;
            // chunk 0 already staged for nh==0 (above); stage here for nh==1
            if (nh == 1) {
                stage_tile(sb, STG(0, 2), bh, HID, tid);
                stage_tile(sb, STG(0, 3), bl, HID, tid);
                CP_COMMIT();
            }
#pragma unroll
            for (int mt = 0; mt < 2; ++mt)
#pragma unroll
                for (int nt = 0; nt < 8; ++nt)
#pragma unroll
                    for (int q = 0; q < 4; ++q) c[mt][nt][q] = 0.f;

            for (int ch = 0; ch < 4; ++ch) {
                if (ch < 3) {
                    int s = (ch + 1) & 1, ko = (ch + 1) * 32;
                    stage_tile(sb, STG(s, 2), bh + ko, HID, tid);
                    stage_tile(sb, STG(s, 3), bl + ko, HID, tid);
                    CP_COMMIT();
                    CP_WAIT1();
                } else {
                    CP_WAIT0();
                }
                __syncthreads();
                int s = ch & 1;
                mma_chunk(c, smem, HOF(ch, 0), HOF(ch, 1), STG(s, 2), STG(s, 3),
                          wm, wn, lr, lc);
                __syncthreads();
            }

            // epilogue: out += D3 (p already folded into h2)
#pragma unroll
            for (int mt = 0; mt < 2; ++mt)
#pragma unroll
                for (int nt = 0; nt < 8; ++nt)
#pragma unroll
                    for (int pr = 0; pr < 2; ++pr) {
                        int m   = wm * 32 + mt * 16 + lr + pr * 8;
                        int col = nh * 128 + wn * 64 + nt * 8 + lc * 2;
                        float* o = out + (size_t)(b0 + m) * LAT + col;
                        float2 v = *reinterpret_cast<float2*>(o);
                        v.x += c[mt][nt][pr * 2];
                        v.y += c[mt][nt][pr * 2 + 1];
                        *reinterpret_cast<float2*>(o) = v;
                    }
        }
    }  // experts
}

// ============================== launch ======================================
extern "C" void kernel_launch(void* const* d_in, const int* in_sizes, int n_in,
                              void* d_out, int out_size) {
    const float* cond = (const float*)d_in[0];
    const float* u    = (const float*)d_in[1];
    const float* tau  = (const float*)d_in[2];
    const float* p    = (const float*)d_in[3];
    const float* W1   = (const float*)d_in[4];
    const float* b1   = (const float*)d_in[5];
    const float* W2   = (const float*)d_in[6];
    const float* b2   = (const float*)d_in[7];
    const float* W3   = (const float*)d_in[8];
    const float* b3   = (const float*)d_in[9];
    float* out = (float*)d_out;

    static int configured = 0;
    if (!configured) {
        cudaFuncSetAttribute(phase_moe_mma,
                             cudaFuncAttributeMaxDynamicSharedMemorySize,
                             SMEM_TOTAL);
        configured = 1;
    }

    convert_x_kernel<<<8192, 256>>>(u, cond);
    convert_w_kernel<<<2048, 256>>>(W1, W2, W3);
    init_out_kernel<<<(B_TOK * LAT) / 256, 256>>>(p, b3, out);
    phase_moe_mma<<<B_TOK / 128, 256, SMEM_TOTAL>>>(tau, p, W1, b1, b2, out);
}

// round 8
// speedup vs baseline: 3.5048x; 1.2470x over previous
#include <cuda_runtime.h>
#include <cuda_bf16.h>
#include <cstdint>

// ============================================================================
// PhaseMoE via mma.sync (HMMA m16n8k16 bf16) with hi/lo 3-MMA split.
// R7 changes: ldmatrix fragment loads, 512 threads (16 warps, 4x4 warp grid),
// 3-stage cp.async pipeline with single syncthreads per chunk.
// tcgen05 unavailable (harness targets compute_103, not 103a).
// ============================================================================

#define B_TOK 32768
#define KEXP  8
#define EIN   1280
#define HID   128
#define LAT   256

#define ROWB   80            // padded bytes per 32-elem bf16 row
#define TILEB  (128 * ROWB)  // 10240 B per 128x32 tile

// smem map: 3 stage buffers x 4 tiles, then 4 h-chunks x hi/lo, then aux
#define STG(s, t) ((uint32_t)(((s) * 4 + (t)) * TILEB))   // t:0 Ahi 1 Alo 2 Bhi 3 Blo
#define HOF(c, h) ((uint32_t)((12 + (c) * 2 + (h)) * TILEB))
#define AUX       ((uint32_t)(20 * TILEB))                 // 204800
#define SMEM_TOTAL (20 * TILEB + 2048)                     // 206848

// ---- bf16 hi/lo scratch (__device__ globals: allocation-free) ----
__device__ __align__(16) __nv_bfloat16 g_xhi[(size_t)B_TOK * EIN];
__device__ __align__(16) __nv_bfloat16 g_xlo[(size_t)B_TOK * EIN];
__device__ __align__(16) __nv_bfloat16 g_w1hi[KEXP * HID * EIN];   // [e][n][k]
__device__ __align__(16) __nv_bfloat16 g_w1lo[KEXP * HID * EIN];
__device__ __align__(16) __nv_bfloat16 g_w2hi[KEXP * HID * HID];
__device__ __align__(16) __nv_bfloat16 g_w2lo[KEXP * HID * HID];
__device__ __align__(16) __nv_bfloat16 g_w3hi[KEXP * LAT * HID];
__device__ __align__(16) __nv_bfloat16 g_w3lo[KEXP * LAT * HID];

// ============================ helpers =======================================
__device__ __forceinline__ uint32_t smem_u32(const void* p) {
    uint32_t a;
    asm("{ .reg .u64 t; cvta.to.shared.u64 t, %1; cvt.u32.u64 %0, t; }"
        : "=r"(a) : "l"(p));
    return a;
}
__device__ __forceinline__ void cpasync16(uint32_t dst, const void* src) {
    asm volatile("cp.async.cg.shared.global [%0], [%1], 16;"
                 :: "r"(dst), "l"(src));
}
#define CP_COMMIT() asm volatile("cp.async.commit_group;" ::: "memory")
#define CP_WAIT1()  asm volatile("cp.async.wait_group 1;" ::: "memory")

__device__ __forceinline__ void ldsm4(uint32_t addr, uint32_t* r) {
    asm volatile("ldmatrix.sync.aligned.m8n8.x4.shared.b16 {%0,%1,%2,%3}, [%4];"
                 : "=r"(r[0]), "=r"(r[1]), "=r"(r[2]), "=r"(r[3]) : "r"(addr));
}

__device__ __forceinline__ void mma16816(float* c, const uint32_t* a,
                                         uint32_t b0, uint32_t b1) {
    asm volatile(
        "mma.sync.aligned.m16n8k16.row.col.f32.bf16.bf16.f32 "
        "{%0,%1,%2,%3}, {%4,%5,%6,%7}, {%8,%9}, {%0,%1,%2,%3};"
        : "+f"(c[0]), "+f"(c[1]), "+f"(c[2]), "+f"(c[3])
        : "r"(a[0]), "r"(a[1]), "r"(a[2]), "r"(a[3]), "r"(b0), "r"(b1));
}

// stage helpers: 512 threads, one 16B cp.async per thread per tile
__device__ __forceinline__ void stage4(uint32_t sb, int st,
        const __nv_bfloat16* xh, const __nv_bfloat16* xl,
        const __nv_bfloat16* wh, const __nv_bfloat16* wl,
        int lda, int ldb, int tid) {
    int row = tid >> 2, c16 = tid & 3;
    uint32_t d = sb + STG(st, 0) + row * ROWB + c16 * 16;
    size_t ao = (size_t)row * lda * 2 + c16 * 16;
    size_t bo = (size_t)row * ldb * 2 + c16 * 16;
    cpasync16(d,             (const char*)xh + ao);
    cpasync16(d + TILEB,     (const char*)xl + ao);
    cpasync16(d + 2 * TILEB, (const char*)wh + bo);
    cpasync16(d + 3 * TILEB, (const char*)wl + bo);
}
__device__ __forceinline__ void stage2(uint32_t sb, int st,
        const __nv_bfloat16* wh, const __nv_bfloat16* wl, int ldb, int tid) {
    int row = tid >> 2, c16 = tid & 3;
    uint32_t d = sb + STG(st, 2) + row * ROWB + c16 * 16;
    size_t bo = (size_t)row * ldb * 2 + c16 * 16;
    cpasync16(d,         (const char*)wh + bo);
    cpasync16(d + TILEB, (const char*)wl + bo);
}

// one 32-wide K chunk of the 3-MMA split for a 32x32 warp tile
__device__ __forceinline__ void mma_chunk(float c[2][4][4], uint32_t sb,
        uint32_t Ahi, uint32_t Alo, uint32_t Bhi, uint32_t Blo,
        int wm, int wn, uint32_t aoff, uint32_t boff) {
#pragma unroll
    for (int ks = 0; ks < 2; ++ks) {
        uint32_t ah[2][4], al[2][4], bh[2][4], bl[2][4];
#pragma unroll
        for (int mt = 0; mt < 2; ++mt) {
            uint32_t base = (uint32_t)((wm * 32 + mt * 16) * ROWB + ks * 32) + aoff;
            ldsm4(sb + Ahi + base, ah[mt]);
            ldsm4(sb + Alo + base, al[mt]);
        }
#pragma unroll
        for (int pr = 0; pr < 2; ++pr) {
            uint32_t base = (uint32_t)((wn * 32 + pr * 16) * ROWB + ks * 32) + boff;
            ldsm4(sb + Bhi + base, bh[pr]);
            ldsm4(sb + Blo + base, bl[pr]);
        }
#pragma unroll
        for (int mt = 0; mt < 2; ++mt)
#pragma unroll
            for (int nt = 0; nt < 4; ++nt) {
                int pr = nt >> 1, hf = (nt & 1) * 2;
                mma16816(c[mt][nt], ah[mt], bh[pr][hf], bh[pr][hf + 1]);
                mma16816(c[mt][nt], ah[mt], bl[pr][hf], bl[pr][hf + 1]);
                mma16816(c[mt][nt], al[mt], bh[pr][hf], bh[pr][hf + 1]);
            }
    }
}

__device__ __forceinline__ void split_pack(float h0, float h1,
                                           uint32_t& hip, uint32_t& lop) {
    __nv_bfloat16 h0h = __float2bfloat16(h0);
    __nv_bfloat16 h1h = __float2bfloat16(h1);
    hip = (uint32_t)__bfloat16_as_ushort(h0h) |
          ((uint32_t)__bfloat16_as_ushort(h1h) << 16);
    lop = (uint32_t)__bfloat16_as_ushort(__float2bfloat16(h0 - __bfloat162float(h0h))) |
          ((uint32_t)__bfloat16_as_ushort(__float2bfloat16(h1 - __bfloat162float(h1h))) << 16);
}

#define ZERO_C() do { \
    _Pragma("unroll") for (int mt = 0; mt < 2; ++mt) \
    _Pragma("unroll") for (int nt = 0; nt < 4; ++nt) \
    _Pragma("unroll") for (int q = 0; q < 4; ++q) c[mt][nt][q] = 0.f; } while (0)

// ======================= prep kernels =======================================
__global__ void convert_x_kernel(const float* __restrict__ u,
                                 const float* __restrict__ cond) {
    const int total = B_TOK * EIN;
    for (int i = blockIdx.x * blockDim.x + threadIdx.x; i < total;
         i += gridDim.x * blockDim.x) {
        int b = i / EIN, k = i - b * EIN;
        float v = (k < 256) ? u[(size_t)b * 256 + k]
                            : cond[(size_t)b * 1024 + (k - 256)];
        __nv_bfloat16 hi = __float2bfloat16(v);
        g_xhi[i] = hi;
        g_xlo[i] = __float2bfloat16(v - __bfloat162float(hi));
    }
}

__global__ void convert_w_kernel(const float* __restrict__ W1,
                                 const float* __restrict__ W2,
                                 const float* __restrict__ W3) {
    const int N1 = KEXP * HID * EIN;
    const int N2 = KEXP * HID * HID;
    const int N3 = KEXP * LAT * HID;
    const int total = N1 + N2 + N3;
    for (int i = blockIdx.x * blockDim.x + threadIdx.x; i < total;
         i += gridDim.x * blockDim.x) {
        float v;
        __nv_bfloat16 *dh, *dl;
        if (i < N1) {
            int e = i / (HID * EIN), r = i - e * (HID * EIN);
            int n = r / EIN, k = r - n * EIN;
            v = W1[((size_t)e * 1281 + k) * HID + n];
            dh = &g_w1hi[i]; dl = &g_w1lo[i];
        } else if (i < N1 + N2) {
            int j = i - N1;
            int e = j / (HID * HID), r = j - e * (HID * HID);
            int n = r / HID, k = r - n * HID;
            v = W2[((size_t)e * HID + k) * HID + n];
            dh = &g_w2hi[j]; dl = &g_w2lo[j];
        } else {
            int j = i - N1 - N2;
            int e = j / (LAT * HID), r = j - e * (LAT * HID);
            int n = r / HID, k = r - n * HID;
            v = W3[((size_t)e * HID + k) * LAT + n];
            dh = &g_w3hi[j]; dl = &g_w3lo[j];
        }
        __nv_bfloat16 hi = __float2bfloat16(v);
        *dh = hi;
        *dl = __float2bfloat16(v - __bfloat162float(hi));
    }
}

__global__ void init_out_kernel(const float* __restrict__ p_hat,
                                const float* __restrict__ b3,
                                float* __restrict__ out) {
    int i = blockIdx.x * blockDim.x + threadIdx.x;   // over B_TOK*LAT
    int b = i >> 8, c = i & 255;
    float s = 0.f;
#pragma unroll
    for (int k = 0; k < KEXP; ++k)
        s = fmaf(p_hat[(size_t)b * KEXP + k], b3[k * LAT + c], s);
    out[i] = s;
}

// =========================== main kernel ====================================
__global__ __launch_bounds__(512, 1)
void phase_moe_mma(const float* __restrict__ tau,
                   const float* __restrict__ p_hat,
                   const float* __restrict__ W1,
                   const float* __restrict__ b1,
                   const float* __restrict__ b2,
                   float* __restrict__ out) {
    extern __shared__ __align__(128) char smem[];
    const uint32_t sb = smem_u32(smem);
    const int tid  = threadIdx.x;
    const int lane = tid & 31;
    const int w    = tid >> 5;
    const int wm   = w >> 2, wn = w & 3;
    const int lr   = lane >> 2, lc = lane & 3;
    const int b0   = blockIdx.x * 128;

    // per-lane ldmatrix address offsets (A: 16x16 x4 ; B: 16rows x 16k x4)
    const uint32_t aoff = (uint32_t)(((lane & 7) + ((lane >> 3) & 1) * 8) * ROWB
                                     + ((lane >> 4) & 1) * 16);
    const uint32_t boff = (uint32_t)(((lane & 7) + ((lane >> 4) & 1) * 8) * ROWB
                                     + ((lane >> 3) & 1) * 16);

    float* b1s  = reinterpret_cast<float*>(smem + AUX);          // 128
    float* b2s  = reinterpret_cast<float*>(smem + AUX + 512);    // 128
    float* w1l  = reinterpret_cast<float*>(smem + AUX + 1024);   // 128
    float* taus = reinterpret_cast<float*>(smem + AUX + 1536);   // 128

    if (tid < 128) taus[tid] = tau[b0 + tid];

    const __nv_bfloat16* xh = g_xhi + (size_t)b0 * EIN;
    const __nv_bfloat16* xl = g_xlo + (size_t)b0 * EIN;

    float c[2][4][4];

    for (int e = 0; e < KEXP; ++e) {
        __syncthreads();   // buffers + bias smem free for reuse
        if (tid < 128) {
            b1s[tid] = b1[e * HID + tid];
            b2s[tid] = b2[e * HID + tid];
            w1l[tid] = W1[((size_t)e * 1281 + 1280) * HID + tid];
        }

        // ---------------- layer 1: K=1280, 40 chunks ------------------------
        const __nv_bfloat16* w1h = g_w1hi + (size_t)e * HID * EIN;
        const __nv_bfloat16* w1o = g_w1lo + (size_t)e * HID * EIN;
        ZERO_C();
        stage4(sb, 0, xh,      xl,      w1h,      w1o,      EIN, EIN, tid); CP_COMMIT();
        stage4(sb, 1, xh + 32, xl + 32, w1h + 32, w1o + 32, EIN, EIN, tid); CP_COMMIT();
        for (int ch = 0; ch < 40; ++ch) {
            CP_WAIT1();
            __syncthreads();
            if (ch + 2 < 40) {
                int ko = (ch + 2) * 32;
                stage4(sb, (ch + 2) % 3, xh + ko, xl + ko, w1h + ko, w1o + ko,
                       EIN, EIN, tid);
            }
            CP_COMMIT();
            int st = ch % 3;
            mma_chunk(c, sb, STG(st, 0), STG(st, 1), STG(st, 2), STG(st, 3),
                      wm, wn, aoff, boff);
        }
        __syncthreads();   // all warps done reading stage buffers

        // prefetch L2 chunks 0,1 (overlaps epilogue)
        const __nv_bfloat16* w2h = g_w2hi + (size_t)e * HID * HID;
        const __nv_bfloat16* w2l = g_w2lo + (size_t)e * HID * HID;
        stage2(sb, 0, w2h,      w2l,      HID, tid); CP_COMMIT();
        stage2(sb, 1, w2h + 32, w2l + 32, HID, tid); CP_COMMIT();

        // L1 epilogue: +bias +tau*w1last, silu, split -> h tiles (chunk = wn)
#pragma unroll
        for (int mt = 0; mt < 2; ++mt)
#pragma unroll
            for (int nt = 0; nt < 4; ++nt)
#pragma unroll
                for (int pr = 0; pr < 2; ++pr) {
                    int m   = wm * 32 + mt * 16 + pr * 8 + lr;
                    int col = wn * 32 + nt * 8 + lc * 2;
                    float t  = taus[m];
                    float v0 = c[mt][nt][pr * 2]     + b1s[col]     + t * w1l[col];
                    float v1 = c[mt][nt][pr * 2 + 1] + b1s[col + 1] + t * w1l[col + 1];
                    float h0 = v0 / (1.f + __expf(-v0));
                    float h1 = v1 / (1.f + __expf(-v1));
                    uint32_t hip, lop;
                    split_pack(h0, h1, hip, lop);
                    uint32_t byte = (uint32_t)(m * ROWB + (nt * 8 + lc * 2) * 2);
                    *(uint32_t*)(smem + HOF(wn, 0) + byte) = hip;
                    *(uint32_t*)(smem + HOF(wn, 1) + byte) = lop;
                }
        __syncthreads();   // h visible to all warps

        // ---------------- layer 2: K=128, 4 chunks --------------------------
        ZERO_C();
        for (int ch = 0; ch < 4; ++ch) {
            CP_WAIT1();
            __syncthreads();
            if (ch + 2 < 4) {
                int ko = (ch + 2) * 32;
                stage2(sb, (ch + 2) % 3, w2h + ko, w2l + ko, HID, tid);
            }
            CP_COMMIT();
            int st = ch % 3;
            mma_chunk(c, sb, HOF(ch, 0), HOF(ch, 1), STG(st, 2), STG(st, 3),
                      wm, wn, aoff, boff);
        }
        __syncthreads();

        // prefetch L3 nh=0 chunks 0,1
        const __nv_bfloat16* w3h = g_w3hi + (size_t)e * LAT * HID;
        const __nv_bfloat16* w3l = g_w3lo + (size_t)e * LAT * HID;
        stage2(sb, 0, w3h,      w3l,      HID, tid); CP_COMMIT();
        stage2(sb, 1, w3h + 32, w3l + 32, HID, tid); CP_COMMIT();

        // L2 epilogue: +bias, silu, *p -> h tiles
#pragma unroll
        for (int mt = 0; mt < 2; ++mt)
#pragma unroll
            for (int nt = 0; nt < 4; ++nt)
#pragma unroll
                for (int pr = 0; pr < 2; ++pr) {
                    int m   = wm * 32 + mt * 16 + pr * 8 + lr;
                    int col = wn * 32 + nt * 8 + lc * 2;
                    float pe = p_hat[(size_t)(b0 + m) * KEXP + e];
                    float v0 = c[mt][nt][pr * 2]     + b2s[col];
                    float v1 = c[mt][nt][pr * 2 + 1] + b2s[col + 1];
                    float h0 = pe * (v0 / (1.f + __expf(-v0)));
                    float h1 = pe * (v1 / (1.f + __expf(-v1)));
                    uint32_t hip, lop;
                    split_pack(h0, h1, hip, lop);
                    uint32_t byte = (uint32_t)(m * ROWB + (nt * 8 + lc * 2) * 2);
                    *(uint32_t*)(smem + HOF(wn, 0) + byte) = hip;
                    *(uint32_t*)(smem + HOF(wn, 1) + byte) = lop;
                }
        __syncthreads();

        // ---------------- layer 3: two 128-col halves, K=128 ----------------
        for (int nh = 0; nh < 2; ++nh) {
            const __nv_bfloat16* bh = w3h + (size_t)nh * 128 * HID;
            const __nv_bfloat16* bl = w3l + (size_t)nh * 128 * HID;
            if (nh == 1) {
                __syncthreads();   // nh=0 readers done with stage buffers
                stage2(sb, 0, bh,      bl,      HID, tid); CP_COMMIT();
                stage2(sb, 1, bh + 32, bl + 32, HID, tid); CP_COMMIT();
            }
            ZERO_C();
            for (int ch = 0; ch < 4; ++ch) {
                CP_WAIT1();
                __syncthreads();
                if (ch + 2 < 4) {
                    int ko = (ch + 2) * 32;
                    stage2(sb, (ch + 2) % 3, bh + ko, bl + ko, HID, tid);
                }
                CP_COMMIT();
                int st = ch % 3;
                mma_chunk(c, sb, HOF(ch, 0), HOF(ch, 1), STG(st, 2), STG(st, 3),
                          wm, wn, aoff, boff);
            }
            // epilogue: out += D3 (p folded into h2; base = sum_k p*b3 via init)
#pragma unroll
            for (int mt = 0; mt < 2; ++mt)
#pragma unroll
                for (int nt = 0; nt < 4; ++nt)
#pragma unroll
                    for (int pr = 0; pr < 2; ++pr) {
                        int m   = wm * 32 + mt * 16 + pr * 8 + lr;
                        int col = nh * 128 + wn * 32 + nt * 8 + lc * 2;
                        float* o = out + (size_t)(b0 + m) * LAT + col;
                        float2 v = *reinterpret_cast<float2*>(o);
                        v.x += c[mt][nt][pr * 2];
                        v.y += c[mt][nt][pr * 2 + 1];
                        *reinterpret_cast<float2*>(o) = v;
                    }
        }
    }  // experts
}

// ============================== launch ======================================
extern "C" void kernel_launch(void* const* d_in, const int* in_sizes, int n_in,
                              void* d_out, int out_size) {
    const float* cond = (const float*)d_in[0];
    const float* u    = (const float*)d_in[1];
    const float* tau  = (const float*)d_in[2];
    const float* p    = (const float*)d_in[3];
    const float* W1   = (const float*)d_in[4];
    const float* b1   = (const float*)d_in[5];
    const float* W2   = (const float*)d_in[6];
    const float* b2   = (const float*)d_in[7];
    const float* W3   = (const float*)d_in[8];
    const float* b3   = (const float*)d_in[9];
    float* out = (float*)d_out;

    static int configured = 0;
    if (!configured) {
        cudaFuncSetAttribute(phase_moe_mma,
                             cudaFuncAttributeMaxDynamicSharedMemorySize,
                             SMEM_TOTAL);
        configured = 1;
    }

    convert_x_kernel<<<8192, 256>>>(u, cond);
    convert_w_kernel<<<2048, 256>>>(W1, W2, W3);
    init_out_kernel<<<(B_TOK * LAT) / 256, 256>>>(p, b3, out);
    phase_moe_mma<<<B_TOK / 128, 512, SMEM_TOTAL>>>(tau, p, W1, b1, b2, out);
}